// round 1
// baseline (speedup 1.0000x reference)
#include <cuda_runtime.h>
#include <cstdint>

#define EDIM   8
#define NCODES 1024
#define NPAIR  512          // NCODES/2
#define SP     32768        // 32*32*32 spatial per batch
#define THREADS 256

typedef unsigned long long ull;

// ---- device scratch (no allocations allowed; reset by vq_init each launch) ----
__device__ float g_lossAcc;
__device__ int   g_used[NCODES];

// ---- packed f32x2 helpers (Blackwell FFMA2 path, PTX-only) ----
__device__ __forceinline__ ull pack2(float lo, float hi){
    ull d;
    asm("mov.b64 %0, {%1, %2};" : "=l"(d)
        : "r"(__float_as_uint(lo)), "r"(__float_as_uint(hi)));
    return d;
}
__device__ __forceinline__ void unpack2(ull v, float& lo, float& hi){
    unsigned a, b;
    asm("mov.b64 {%0, %1}, %2;" : "=r"(a), "=r"(b) : "l"(v));
    lo = __uint_as_float(a); hi = __uint_as_float(b);
}
__device__ __forceinline__ ull fma2(ull a, ull b, ull c){
    ull d; asm("fma.rn.f32x2 %0, %1, %2, %3;" : "=l"(d) : "l"(a), "l"(b), "l"(c));
    return d;
}
__device__ __forceinline__ ull mul2(ull a, ull b){
    ull d; asm("mul.rn.f32x2 %0, %1, %2;" : "=l"(d) : "l"(a), "l"(b));
    return d;
}
__device__ __forceinline__ ull add2(ull a, ull b){
    ull d; asm("add.rn.f32x2 %0, %1, %2;" : "=l"(d) : "l"(a), "l"(b));
    return d;
}

// ---- reset scratch (runs at every graph replay) ----
__global__ void vq_init(){
    if (threadIdx.x == 0) g_lossAcc = 0.f;
    g_used[threadIdx.x] = 0;        // launched with 1024 threads
}

// ---- main: each thread handles 2 query vectors (n and n + Nvec/2) ----
__global__ __launch_bounds__(THREADS) void vq_main(
    const float* __restrict__ z,
    const float* __restrict__ emb,
    float* __restrict__ out,
    int Nvec)
{
    __shared__ __align__(16) float2 sE[NPAIR * EDIM];  // pair-packed codebook, 32KB
    __shared__ __align__(16) float  sEE[NCODES];       // ||e||^2, 4KB
    __shared__ float sRed[THREADS / 32];

    // Stage codebook: sE[p*8+c] = (e[2p][c], e[2p+1][c])
    for (int i = threadIdx.x; i < NPAIR * EDIM; i += THREADS){
        int p = i >> 3, c = i & 7;
        sE[i] = make_float2(emb[(2*p)*EDIM + c], emb[(2*p+1)*EDIM + c]);
    }
    for (int j = threadIdx.x; j < NCODES; j += THREADS){
        float s = 0.f;
        #pragma unroll
        for (int c = 0; c < EDIM; c++){ float e = emb[j*EDIM + c]; s = fmaf(e, e, s); }
        sEE[j] = s;
    }
    __syncthreads();

    const int half = Nvec >> 1;
    const int t = blockIdx.x * THREADS + threadIdx.x;
    float lossLocal = 0.f;

    if (t < half) {
        const int n0 = t, n1 = t + half;
        const int b0 = n0 >> 15, s0 = n0 & (SP - 1);
        const int b1 = n1 >> 15, s1 = n1 & (SP - 1);
        const float* z0p = z + (size_t)b0 * (EDIM * SP) + s0;
        const float* z1p = z + (size_t)b1 * (EDIM * SP) + s1;

        float z0[EDIM], z1[EDIM];
        #pragma unroll
        for (int c = 0; c < EDIM; c++){ z0[c] = z0p[c * SP]; z1[c] = z1p[c * SP]; }

        float zz0 = 0.f, zz1 = 0.f;
        #pragma unroll
        for (int c = 0; c < EDIM; c++){
            zz0 = fmaf(z0[c], z0[c], zz0);
            zz1 = fmaf(z1[c], z1[c], zz1);
        }

        ull zp0[EDIM], zp1[EDIM];
        #pragma unroll
        for (int c = 0; c < EDIM; c++){
            zp0[c] = pack2(z0[c], z0[c]);
            zp1[c] = pack2(z1[c], z1[c]);
        }
        const ull zzp0 = pack2(zz0, zz0);
        const ull zzp1 = pack2(zz1, zz1);
        const ull m2   = pack2(-2.f, -2.f);

        float best0 = 3.4e38f, best1 = 3.4e38f;
        int bi0 = 0, bi1 = 0;

        #pragma unroll 4
        for (int p = 0; p < NPAIR; p++){
            const ulonglong2* ep = reinterpret_cast<const ulonglong2*>(sE + p * EDIM);
            const ulonglong2 e01 = ep[0];
            const ulonglong2 e23 = ep[1];
            const ulonglong2 e45 = ep[2];
            const ulonglong2 e67 = ep[3];
            const ull eep = *reinterpret_cast<const ull*>(sEE + 2 * p);

            ull a0 = mul2(zp0[0], e01.x);
            a0 = fma2(zp0[1], e01.y, a0);
            a0 = fma2(zp0[2], e23.x, a0);
            a0 = fma2(zp0[3], e23.y, a0);
            a0 = fma2(zp0[4], e45.x, a0);
            a0 = fma2(zp0[5], e45.y, a0);
            a0 = fma2(zp0[6], e67.x, a0);
            a0 = fma2(zp0[7], e67.y, a0);
            ull d0 = fma2(a0, m2, add2(eep, zzp0));
            float d00, d01; unpack2(d0, d00, d01);
            if (d00 < best0){ best0 = d00; bi0 = 2*p;     }
            if (d01 < best0){ best0 = d01; bi0 = 2*p + 1; }

            ull a1 = mul2(zp1[0], e01.x);
            a1 = fma2(zp1[1], e01.y, a1);
            a1 = fma2(zp1[2], e23.x, a1);
            a1 = fma2(zp1[3], e23.y, a1);
            a1 = fma2(zp1[4], e45.x, a1);
            a1 = fma2(zp1[5], e45.y, a1);
            a1 = fma2(zp1[6], e67.x, a1);
            a1 = fma2(zp1[7], e67.y, a1);
            ull d1 = fma2(a1, m2, add2(eep, zzp1));
            float d10, d11; unpack2(d1, d10, d11);
            if (d10 < best1){ best1 = d10; bi1 = 2*p;     }
            if (d11 < best1){ best1 = d11; bi1 = 2*p + 1; }
        }

        // Epilogue: gather z_q, accumulate loss, write idx, mark used
        const int n_z = Nvec * EDIM;
        {
            const int p = bi0 >> 1, sel = bi0 & 1;
            float* o = out + (size_t)b0 * (EDIM * SP) + s0;
            #pragma unroll
            for (int c = 0; c < EDIM; c++){
                float2 ev = sE[p * EDIM + c];
                float e = sel ? ev.y : ev.x;
                o[c * SP] = e;
                float df = e - z0[c];
                lossLocal = fmaf(df, df, lossLocal);
            }
            out[n_z + 2 + n0] = (float)bi0;
            g_used[bi0] = 1;
        }
        {
            const int p = bi1 >> 1, sel = bi1 & 1;
            float* o = out + (size_t)b1 * (EDIM * SP) + s1;
            #pragma unroll
            for (int c = 0; c < EDIM; c++){
                float2 ev = sE[p * EDIM + c];
                float e = sel ? ev.y : ev.x;
                o[c * SP] = e;
                float df = e - z1[c];
                lossLocal = fmaf(df, df, lossLocal);
            }
            out[n_z + 2 + n1] = (float)bi1;
            g_used[bi1] = 1;
        }
    }

    // Block-reduce loss, one atomicAdd per block
    #pragma unroll
    for (int o = 16; o > 0; o >>= 1)
        lossLocal += __shfl_down_sync(0xffffffff, lossLocal, o);
    const int lane = threadIdx.x & 31, w = threadIdx.x >> 5;
    if (lane == 0) sRed[w] = lossLocal;
    __syncthreads();
    if (threadIdx.x < THREADS / 32){
        float v = sRed[threadIdx.x];
        #pragma unroll
        for (int o = (THREADS / 64); o > 0; o >>= 1)
            v += __shfl_down_sync(0xff, v, o);
        if (threadIdx.x == 0) atomicAdd(&g_lossAcc, v);
    }
}

// ---- finalize: loss scalar + unique count ----
__global__ void vq_fin(float* __restrict__ out, int n_z){
    int pred = (g_used[threadIdx.x] != 0);     // 1024 threads
    int cnt = __syncthreads_count(pred);
    if (threadIdx.x == 0){
        // loss = beta*mean + mean = 1.25 * sum((z_q - z)^2) / n_z
        out[n_z]     = 1.25f * g_lossAcc / (float)n_z;
        out[n_z + 1] = (float)cnt;
    }
}

extern "C" void kernel_launch(void* const* d_in, const int* in_sizes, int n_in,
                              void* d_out, int out_size)
{
    const float* z   = (const float*)d_in[0];
    const float* emb = (const float*)d_in[1];
    float* out = (float*)d_out;

    const int n_z  = in_sizes[0];      // 2,097,152
    const int Nvec = n_z / EDIM;       // 262,144

    vq_init<<<1, NCODES>>>();
    const int half = Nvec / 2;
    vq_main<<<(half + THREADS - 1) / THREADS, THREADS>>>(z, emb, out, Nvec);
    vq_fin<<<1, NCODES>>>(out, n_z);
}

// round 2
// speedup vs baseline: 1.0980x; 1.0980x over previous
#include <cuda_runtime.h>
#include <cstdint>

#define EDIM    8
#define NCODES  1024
#define NPAIR   512          // NCODES/2
#define SP      32768        // 32*32*32 spatial per batch
#define THREADS 128
#define QPT     4            // queries per thread

typedef unsigned long long ull;

// ---- device scratch (no allocations; overwrite semantics, self-cleaning) ----
__device__ float g_partial[4096];   // per-block loss partial sums (overwritten each run)
__device__ int   g_used[NCODES];    // set by main, counted+reset by fin

// ---- packed f32x2 helpers (Blackwell FFMA2 path, PTX-only) ----
__device__ __forceinline__ ull pack2(float lo, float hi){
    ull d;
    asm("mov.b64 %0, {%1, %2};" : "=l"(d)
        : "r"(__float_as_uint(lo)), "r"(__float_as_uint(hi)));
    return d;
}
__device__ __forceinline__ ull fma2(ull a, ull b, ull c){
    ull d; asm("fma.rn.f32x2 %0, %1, %2, %3;" : "=l"(d) : "l"(a), "l"(b), "l"(c));
    return d;
}
__device__ __forceinline__ ull mul2(ull a, ull b){
    ull d; asm("mul.rn.f32x2 %0, %1, %2;" : "=l"(d) : "l"(a), "l"(b));
    return d;
}
__device__ __forceinline__ ull add2(ull a, ull b){
    ull d; asm("add.rn.f32x2 %0, %1, %2;" : "=l"(d) : "l"(a), "l"(b));
    return d;
}
union U64F2 { ull u; float2 f; };
__device__ __forceinline__ float2 asf2(ull v){ U64F2 x; x.u = v; return x.f; }

// Bit-exact pair distance: d_pair = fma2(dot2, {-2,-2}, add2(ee2, zz2))
// (this exact op structure reproduces the reference's (zz+ee) rounding; do not change)
__device__ __forceinline__ ull pair_dist(const ulonglong2* ep, ull eep,
                                         const ull* zp, ull zzp, ull m2){
    const ulonglong2 e01 = ep[0];
    const ulonglong2 e23 = ep[1];
    const ulonglong2 e45 = ep[2];
    const ulonglong2 e67 = ep[3];
    ull a = mul2(zp[0], e01.x);
    a = fma2(zp[1], e01.y, a);
    a = fma2(zp[2], e23.x, a);
    a = fma2(zp[3], e23.y, a);
    a = fma2(zp[4], e45.x, a);
    a = fma2(zp[5], e45.y, a);
    a = fma2(zp[6], e67.x, a);
    a = fma2(zp[7], e67.y, a);
    return fma2(a, m2, add2(eep, zzp));
}

// ---- main: each thread handles QPT=4 query vectors ----
__global__ __launch_bounds__(THREADS, 4) void vq_main(
    const float* __restrict__ z,
    const float* __restrict__ emb,
    float* __restrict__ out,
    int Nvec)
{
    __shared__ __align__(16) float2 sE[NPAIR * EDIM];  // pair-packed codebook, 32KB
    __shared__ __align__(16) float  sEE[NCODES];       // ||e||^2, 4KB
    __shared__ float sRed[THREADS / 32];

    // Stage codebook: sE[p*8+c] = (e[2p][c], e[2p+1][c])
    for (int i = threadIdx.x; i < NPAIR * EDIM; i += THREADS){
        int p = i >> 3, c = i & 7;
        sE[i] = make_float2(emb[(2*p)*EDIM + c], emb[(2*p+1)*EDIM + c]);
    }
    for (int j = threadIdx.x; j < NCODES; j += THREADS){
        float s = 0.f;
        #pragma unroll
        for (int c = 0; c < EDIM; c++){ float e = emb[j*EDIM + c]; s = fmaf(e, e, s); }
        sEE[j] = s;
    }
    __syncthreads();

    const int quarter = Nvec >> 2;
    const int t = blockIdx.x * THREADS + threadIdx.x;
    float lossLocal = 0.f;

    if (t < quarter) {
        int   nq[QPT];
        int   bq[QPT], sq[QPT];
        float zq[QPT][EDIM];
        ull   zp[QPT][EDIM];
        ull   zzp[QPT];

        #pragma unroll
        for (int q = 0; q < QPT; q++){
            nq[q] = t + q * quarter;
            bq[q] = nq[q] >> 15;
            sq[q] = nq[q] & (SP - 1);
            const float* zptr = z + (size_t)bq[q] * (EDIM * SP) + sq[q];
            float zz = 0.f;
            #pragma unroll
            for (int c = 0; c < EDIM; c++){
                float v = zptr[c * SP];
                zq[q][c] = v;
                zz = fmaf(v, v, zz);
            }
            #pragma unroll
            for (int c = 0; c < EDIM; c++) zp[q][c] = pack2(zq[q][c], zq[q][c]);
            zzp[q] = pack2(zz, zz);
        }
        const ull m2 = pack2(-2.f, -2.f);

        float best[QPT];
        int   bip[QPT];          // winning PAIR index
        #pragma unroll
        for (int q = 0; q < QPT; q++){ best[q] = 3.4e38f; bip[q] = 0; }

        #pragma unroll 4
        for (int p = 0; p < NPAIR; p++){
            const ulonglong2* ep = reinterpret_cast<const ulonglong2*>(sE + p * EDIM);
            const ull eep = *reinterpret_cast<const ull*>(sEE + 2 * p);
            #pragma unroll
            for (int q = 0; q < QPT; q++){
                float2 df = asf2(pair_dist(ep, eep, zp[q], zzp[q], m2));
                float dm = fminf(df.x, df.y);
                bool upd = dm < best[q];
                bip[q] = upd ? p : bip[q];
                best[q] = fminf(best[q], dm);
            }
        }

        // Epilogue: resolve even/odd half (bit-exact recompute), gather, loss, idx
        const int n_z = Nvec * EDIM;
        #pragma unroll
        for (int q = 0; q < QPT; q++){
            const int p = bip[q];
            const ulonglong2* ep = reinterpret_cast<const ulonglong2*>(sE + p * EDIM);
            const ull eep = *reinterpret_cast<const ull*>(sEE + 2 * p);
            float2 df = asf2(pair_dist(ep, eep, zp[q], zzp[q], m2));
            const int sel = (df.y < df.x) ? 1 : 0;   // tie -> even (first index)
            const int bi = 2 * p + sel;

            float* o = out + (size_t)bq[q] * (EDIM * SP) + sq[q];
            #pragma unroll
            for (int c = 0; c < EDIM; c++){
                float2 ev = sE[p * EDIM + c];
                float e = sel ? ev.y : ev.x;
                o[c * SP] = e;
                float dfc = e - zq[q][c];
                lossLocal = fmaf(dfc, dfc, lossLocal);
            }
            out[n_z + 2 + nq[q]] = (float)bi;
            g_used[bi] = 1;
        }
    }

    // Block-reduce loss -> deterministic per-block partial (no atomics, no init)
    #pragma unroll
    for (int o = 16; o > 0; o >>= 1)
        lossLocal += __shfl_down_sync(0xffffffff, lossLocal, o);
    const int lane = threadIdx.x & 31, w = threadIdx.x >> 5;
    if (lane == 0) sRed[w] = lossLocal;
    __syncthreads();
    if (threadIdx.x == 0){
        float v = 0.f;
        #pragma unroll
        for (int i = 0; i < THREADS / 32; i++) v += sRed[i];
        g_partial[blockIdx.x] = v;
    }
}

// ---- finalize: loss scalar + unique count; self-cleans g_used ----
__global__ void vq_fin(float* __restrict__ out, int n_z, int nblocks){
    __shared__ float red[32];

    // unique count
    int pred = (g_used[threadIdx.x] != 0);     // 1024 threads
    int cnt = __syncthreads_count(pred);
    g_used[threadIdx.x] = 0;                   // reset for next replay

    // loss reduce over per-block partials
    float s = 0.f;
    for (int i = threadIdx.x; i < nblocks; i += 1024) s += g_partial[i];
    #pragma unroll
    for (int o = 16; o > 0; o >>= 1)
        s += __shfl_down_sync(0xffffffff, s, o);
    const int lane = threadIdx.x & 31, w = threadIdx.x >> 5;
    if (lane == 0) red[w] = s;
    __syncthreads();
    if (threadIdx.x == 0){
        float total = 0.f;
        #pragma unroll
        for (int i = 0; i < 32; i++) total += red[i];
        // loss = beta*mean + mean = 1.25 * sum((z_q - z)^2) / n_z
        out[n_z]     = 1.25f * total / (float)n_z;
        out[n_z + 1] = (float)cnt;
    }
}

extern "C" void kernel_launch(void* const* d_in, const int* in_sizes, int n_in,
                              void* d_out, int out_size)
{
    const float* z   = (const float*)d_in[0];
    const float* emb = (const float*)d_in[1];
    float* out = (float*)d_out;

    const int n_z  = in_sizes[0];      // 2,097,152
    const int Nvec = n_z / EDIM;       // 262,144

    const int quarter = Nvec / 4;
    const int nblocks = (quarter + THREADS - 1) / THREADS;   // 512
    vq_main<<<nblocks, THREADS>>>(z, emb, out, Nvec);
    vq_fin<<<1, NCODES>>>(out, n_z, nblocks);
}

// round 3
// speedup vs baseline: 1.1466x; 1.0443x over previous
#include <cuda_runtime.h>
#include <cstdint>

#define EDIM    8
#define NCODES  1024
#define NPAIR   512          // NCODES/2
#define SP      32768        // 32*32*32 spatial per batch
#define THREADS 128
#define QPT     2            // queries per thread

typedef unsigned long long ull;

// ---- device scratch (no allocations; self-resetting across graph replays) ----
__device__ float    g_partial[4096];   // per-block loss partials (overwritten each run)
__device__ int      g_used[NCODES];    // set by main, counted+reset by finalizer
__device__ unsigned g_ticket = 0;      // completion ticket; finalizer resets to 0

// ---- packed f32x2 helpers (Blackwell FFMA2 path, PTX-only) ----
__device__ __forceinline__ ull pack2(float lo, float hi){
    ull d;
    asm("mov.b64 %0, {%1, %2};" : "=l"(d)
        : "r"(__float_as_uint(lo)), "r"(__float_as_uint(hi)));
    return d;
}
__device__ __forceinline__ ull fma2(ull a, ull b, ull c){
    ull d; asm("fma.rn.f32x2 %0, %1, %2, %3;" : "=l"(d) : "l"(a), "l"(b), "l"(c));
    return d;
}
__device__ __forceinline__ ull mul2(ull a, ull b){
    ull d; asm("mul.rn.f32x2 %0, %1, %2;" : "=l"(d) : "l"(a), "l"(b));
    return d;
}
__device__ __forceinline__ ull add2(ull a, ull b){
    ull d; asm("add.rn.f32x2 %0, %1, %2;" : "=l"(d) : "l"(a), "l"(b));
    return d;
}
union U64F2 { ull u; float2 f; };
__device__ __forceinline__ float2 asf2(ull v){ U64F2 x; x.u = v; return x.f; }

// Bit-exact pair distance: d_pair = fma2(dot2, {-2,-2}, add2(ee2, zz2))
// (this exact op structure reproduces the reference's (zz+ee) rounding; do not change)
__device__ __forceinline__ ull pair_dist(const ulonglong2* ep, ull eep,
                                         const ull* zp, ull zzp, ull m2){
    const ulonglong2 e01 = ep[0];
    const ulonglong2 e23 = ep[1];
    const ulonglong2 e45 = ep[2];
    const ulonglong2 e67 = ep[3];
    ull a = mul2(zp[0], e01.x);
    a = fma2(zp[1], e01.y, a);
    a = fma2(zp[2], e23.x, a);
    a = fma2(zp[3], e23.y, a);
    a = fma2(zp[4], e45.x, a);
    a = fma2(zp[5], e45.y, a);
    a = fma2(zp[6], e67.x, a);
    a = fma2(zp[7], e67.y, a);
    return fma2(a, m2, add2(eep, zzp));
}

// ---- single fused kernel: search + epilogue + ticket-gated finalize ----
__global__ __launch_bounds__(THREADS, 7) void vq_main(
    const float* __restrict__ z,
    const float* __restrict__ emb,
    float* __restrict__ out,
    int Nvec, int nblocks)
{
    __shared__ __align__(16) float2 sE[NPAIR * EDIM];  // pair-packed codebook, 32KB
    __shared__ __align__(16) float  sEE[NCODES];       // ||e||^2, 4KB
    __shared__ float sRed[THREADS / 32];
    __shared__ bool  sLast;

    // Stage codebook: sE[p*8+c] = (e[2p][c], e[2p+1][c])
    for (int i = threadIdx.x; i < NPAIR * EDIM; i += THREADS){
        int p = i >> 3, c = i & 7;
        sE[i] = make_float2(emb[(2*p)*EDIM + c], emb[(2*p+1)*EDIM + c]);
    }
    for (int j = threadIdx.x; j < NCODES; j += THREADS){
        float s = 0.f;
        #pragma unroll
        for (int c = 0; c < EDIM; c++){ float e = emb[j*EDIM + c]; s = fmaf(e, e, s); }
        sEE[j] = s;
    }
    __syncthreads();

    const int part = Nvec >> 1;                 // Nvec / QPT
    const int t = blockIdx.x * THREADS + threadIdx.x;
    float lossLocal = 0.f;

    if (t < part) {
        int nq[QPT], bq[QPT], sq[QPT];
        ull zp[QPT][EDIM];
        ull zzp[QPT];

        #pragma unroll
        for (int q = 0; q < QPT; q++){
            nq[q] = t + q * part;
            bq[q] = nq[q] >> 15;
            sq[q] = nq[q] & (SP - 1);
            const float* zptr = z + (size_t)bq[q] * (EDIM * SP) + sq[q];
            float zz = 0.f;
            #pragma unroll
            for (int c = 0; c < EDIM; c++){
                float v = zptr[c * SP];
                zp[q][c] = pack2(v, v);
                zz = fmaf(v, v, zz);
            }
            zzp[q] = pack2(zz, zz);
        }
        const ull m2 = pack2(-2.f, -2.f);

        float best[QPT];
        int   bip[QPT];                         // winning PAIR index
        #pragma unroll
        for (int q = 0; q < QPT; q++){ best[q] = 3.4e38f; bip[q] = 0; }

        #pragma unroll 4
        for (int p = 0; p < NPAIR; p++){
            const ulonglong2* ep = reinterpret_cast<const ulonglong2*>(sE + p * EDIM);
            const ull eep = *reinterpret_cast<const ull*>(sEE + 2 * p);
            #pragma unroll
            for (int q = 0; q < QPT; q++){
                float2 df = asf2(pair_dist(ep, eep, zp[q], zzp[q], m2));
                float dm = fminf(df.x, df.y);
                bool upd = dm < best[q];
                bip[q] = upd ? p : bip[q];
                best[q] = fminf(best[q], dm);
            }
        }

        // Epilogue: resolve even/odd half (bit-exact recompute), gather, loss, idx
        const int n_z = Nvec * EDIM;
        #pragma unroll
        for (int q = 0; q < QPT; q++){
            const int p = bip[q];
            const ulonglong2* ep = reinterpret_cast<const ulonglong2*>(sE + p * EDIM);
            const ull eep = *reinterpret_cast<const ull*>(sEE + 2 * p);
            float2 df = asf2(pair_dist(ep, eep, zp[q], zzp[q], m2));
            const int sel = (df.y < df.x) ? 1 : 0;   // tie -> even (first index)
            const int bi = 2 * p + sel;

            float* o = out + (size_t)bq[q] * (EDIM * SP) + sq[q];
            #pragma unroll
            for (int c = 0; c < EDIM; c++){
                float2 ev = sE[p * EDIM + c];
                float e = sel ? ev.y : ev.x;
                o[c * SP] = e;
                float zc = asf2(zp[q][c]).x;
                float dfc = e - zc;
                lossLocal = fmaf(dfc, dfc, lossLocal);
            }
            out[n_z + 2 + nq[q]] = (float)bi;
            g_used[bi] = 1;
        }
    }

    // Block-reduce loss -> deterministic per-block partial
    #pragma unroll
    for (int o = 16; o > 0; o >>= 1)
        lossLocal += __shfl_down_sync(0xffffffff, lossLocal, o);
    const int lane = threadIdx.x & 31, w = threadIdx.x >> 5;
    if (lane == 0) sRed[w] = lossLocal;
    __syncthreads();
    if (threadIdx.x == 0){
        float v = 0.f;
        #pragma unroll
        for (int i = 0; i < THREADS / 32; i++) v += sRed[i];
        g_partial[blockIdx.x] = v;
        __threadfence();
        unsigned old = atomicAdd(&g_ticket, 1u);
        sLast = (old == (unsigned)(nblocks - 1));
    }
    __syncthreads();

    // Last block to finish performs finalization (deterministic result)
    if (sLast){
        __threadfence();
        const int n_z = Nvec * EDIM;

        // unique count + reset g_used for next replay
        int cnt = 0;
        for (int i = threadIdx.x; i < NCODES; i += THREADS){
            cnt += (g_used[i] != 0);
            g_used[i] = 0;
        }
        // loss: fixed-order partial sum (thread-strided, then tree-reduced)
        float s = 0.f;
        for (int i = threadIdx.x; i < nblocks; i += THREADS) s += g_partial[i];

        #pragma unroll
        for (int o = 16; o > 0; o >>= 1){
            s   += __shfl_down_sync(0xffffffff, s, o);
            cnt += __shfl_down_sync(0xffffffff, cnt, o);
        }
        __shared__ float rs[THREADS / 32];
        __shared__ int   rc[THREADS / 32];
        if (lane == 0){ rs[w] = s; rc[w] = cnt; }
        __syncthreads();
        if (threadIdx.x == 0){
            float total = 0.f; int ctotal = 0;
            #pragma unroll
            for (int i = 0; i < THREADS / 32; i++){ total += rs[i]; ctotal += rc[i]; }
            // loss = beta*mean + mean = 1.25 * sum((z_q - z)^2) / n_z
            out[n_z]     = 1.25f * total / (float)n_z;
            out[n_z + 1] = (float)ctotal;
            __threadfence();
            g_ticket = 0;                       // reset for next graph replay
        }
    }
}

extern "C" void kernel_launch(void* const* d_in, const int* in_sizes, int n_in,
                              void* d_out, int out_size)
{
    const float* z   = (const float*)d_in[0];
    const float* emb = (const float*)d_in[1];
    float* out = (float*)d_out;

    const int n_z  = in_sizes[0];      // 2,097,152
    const int Nvec = n_z / EDIM;       // 262,144

    const int part = Nvec / QPT;
    const int nblocks = (part + THREADS - 1) / THREADS;   // 1024
    vq_main<<<nblocks, THREADS>>>(z, emb, out, Nvec, nblocks);
}